// round 14
// baseline (speedup 1.0000x reference)
#include <cuda_runtime.h>
#include <cstddef>

#define FULLMASK 0xffffffffu
typedef unsigned long long u64;

// f32x2 packed helpers
__device__ __forceinline__ u64 ffma2(u64 a, u64 b, u64 c) {
    u64 d; asm("fma.rn.f32x2 %0, %1, %2, %3;" : "=l"(d) : "l"(a), "l"(b), "l"(c)); return d;
}
__device__ __forceinline__ u64 fadd2(u64 a, u64 b) {
    u64 d; asm("add.rn.f32x2 %0, %1, %2;" : "=l"(d) : "l"(a), "l"(b)); return d;
}
__device__ __forceinline__ u64 fmul2(u64 a, u64 b) {
    u64 d; asm("mul.rn.f32x2 %0, %1, %2;" : "=l"(d) : "l"(a), "l"(b)); return d;
}
__device__ __forceinline__ u64 pack2(float lo, float hi) {
    u64 d; asm("mov.b64 %0, {%1, %2};" : "=l"(d) : "f"(lo), "f"(hi)); return d;
}
__device__ __forceinline__ float2 unpack2(u64 a) {
    float2 r; asm("mov.b64 {%0, %1}, %2;" : "=f"(r.x), "=f"(r.y) : "l"(a)); return r;
}

// Global scratch
static __device__ __align__(16) float g_patch[16384 * 784];
static __device__ __align__(16) float g_q[16384 * 784];
static __device__ __align__(16) float g_k[16384 * 784];
static __device__ __align__(16) float g_v[16384 * 784];
static __device__ __align__(16) float g_tok2[16384 * 784];
static __device__ __align__(16) float g_q2[16384 * 392];
static __device__ __align__(16) float g_k2[16384 * 392];
static __device__ __align__(16) float g_v2[16384 * 392];
static __device__ unsigned g_c0, g_c1, g_c2, g_c3;

// ---------------------------------------------------------------------------
// Kernel P: grayscale + patch scatter + counter reset.
// ---------------------------------------------------------------------------
__global__ void vitP(const float* __restrict__ x)
{
    int t = blockIdx.x * 256 + threadIdx.x;
    if (t == 0) { g_c0 = 0; g_c1 = 0; g_c2 = 0; g_c3 = 0; }
    if (t >= 16384 * 196) return;
    int b = t / 196;
    int r = t - b * 196;
    int py = r / 7;
    int sx = r - py * 7;
    const float4* xb = (const float4*)(x + (size_t)b * 2352);
    int off = py * 7 + sx;
    float4 c0 = __ldg(xb + off);
    float4 c1 = __ldg(xb + 196 + off);
    float4 c2 = __ldg(xb + 392 + off);
    float4 g;
    g.x = 0.299f * c0.x + 0.587f * c1.x + 0.114f * c2.x;
    g.y = 0.299f * c0.y + 0.587f * c1.y + 0.114f * c2.y;
    g.z = 0.299f * c0.z + 0.587f * c1.z + 0.114f * c2.z;
    g.w = 0.299f * c0.w + 0.587f * c1.w + 0.114f * c2.w;
    int patch = (py >> 2) * 7 + sx;
    *(float4*)(g_patch + (size_t)b * 784 + patch * 16 + (py & 3) * 4) = g;
}

// Packed 16-dot: P0..P7 against weight block (quad stride QS ulonglong2's)
#define PDOT(res, base, qs, bias) {                                          \
    const ulonglong2* _w = (const ulonglong2*)(base);                        \
    ulonglong2 _w0 = _w[0], _w1 = _w[qs], _w2 = _w[2*(qs)], _w3 = _w[3*(qs)];\
    u64 _a = 0ull, _b = 0ull;                                                \
    _a = ffma2(P0, _w0.x, _a); _b = ffma2(P1, _w0.y, _b);                    \
    _a = ffma2(P2, _w1.x, _a); _b = ffma2(P3, _w1.y, _b);                    \
    _a = ffma2(P4, _w2.x, _a); _b = ffma2(P5, _w2.y, _b);                    \
    _a = ffma2(P6, _w3.x, _a); _b = ffma2(P7, _w3.y, _b);                    \
    float2 _f = unpack2(fadd2(_a, _b));                                      \
    res = _f.x + _f.y + (bias); }

// ---------------------------------------------------------------------------
// qkv1: stage-1 projection only. No serial deps — every s independent.
// Half-warp = 1 element (pair claims). 640 threads, weights in SMEM.
// SMEM: 3*12544 + 3*784 = 39984 floats = 159936 B.
// ---------------------------------------------------------------------------
__global__ void __launch_bounds__(640, 1) qkv1(
    const float* __restrict__ pe,
    const float* __restrict__ WQ1,
    const float* __restrict__ WK1,
    const float* __restrict__ WV1)
{
    extern __shared__ float sm[];
    float* sW = sm;          // [w][s][i/4][o][4]
    float* sB = sm + 37632;

    const int tid = threadIdx.x;
    {
        const float* Wg[3] = {WQ1, WK1, WV1};
        for (int w = 0; w < 3; ++w) {
            const float* G = Wg[w];
            float* dst = sW + w * 12544;
            for (int idx = tid; idx < 12544; idx += 640) {
                int s = idx >> 8, r = idx & 255, i = r >> 4, o = r & 15;
                dst[s * 256 + (i >> 2) * 64 + o * 4 + (i & 3)] = G[(s * 16 + o) * 32 + i];
            }
            float* db = sB + w * 784;
            for (int idx = tid; idx < 784; idx += 640) {
                int s = idx >> 4, o = idx & 15;
                const float* gw = G + (s * 16 + o) * 32 + 16;
                const float* pp = pe + s * 16;
                float acc = 0.f;
#pragma unroll
                for (int j = 0; j < 16; ++j) acc = fmaf(pp[j], gw[j], acc);
                db[idx] = acc;
            }
        }
    }
    __syncthreads();

    const int lane = tid & 31;
    const int hh = lane >> 4;
    const int l16 = lane & 15;

    for (;;) {
        unsigned p;
        if (lane == 0) p = atomicAdd(&g_c0, 1u);
        p = __shfl_sync(FULLMASK, p, 0);
        if (p >= 8192) break;
        const int elem = (int)p * 2 + hh;
        const ulonglong2* pvu = (const ulonglong2*)(g_patch + (size_t)elem * 784);
        float* qb = g_q + (size_t)elem * 784;
        float* kb2 = g_k + (size_t)elem * 784;
        float* vb = g_v + (size_t)elem * 784;

#pragma unroll 2
        for (int s = 0; s < 49; ++s) {
            ulonglong2 t0 = __ldg(pvu + s * 4 + 0), t1 = __ldg(pvu + s * 4 + 1);
            ulonglong2 t2 = __ldg(pvu + s * 4 + 2), t3 = __ldg(pvu + s * 4 + 3);
            u64 P0 = t0.x, P1 = t0.y, P2 = t1.x, P3 = t1.y;
            u64 P4 = t2.x, P5 = t2.y, P6 = t3.x, P7 = t3.y;

            float q, k, v;
            PDOT(q, sW + s * 256 + l16 * 4, 8, sB[s * 16 + l16]);
            PDOT(k, sW + 12544 + s * 256 + l16 * 4, 8, sB[784 + s * 16 + l16]);
            PDOT(v, sW + 25088 + s * 256 + l16 * 4, 8, sB[1568 + s * 16 + l16]);
            qb[s * 16 + l16] = q;
            kb2[s * 16 + l16] = k;
            vb[s * 16 + l16] = v;
        }
    }
}

// ---------------------------------------------------------------------------
// gram1: q,k -> S (16x16) -> apply to v -> softmax(16) -> tok2.
// No weights: SMEM = 32 warps * 64 = 8 KB -> 1024 threads = 32 warps/SM.
// Half-warp = 1 element (pair claims).
// ---------------------------------------------------------------------------
__global__ void __launch_bounds__(1024, 1) gram1()
{
    extern __shared__ float sm[];
    const int tid = threadIdx.x;
    const int warpId = tid >> 5;
    const int lane = tid & 31;
    const int hh = lane >> 4;
    const int l16 = lane & 15;
    float* kb = sm + warpId * 64;

    for (;;) {
        unsigned p;
        if (lane == 0) p = atomicAdd(&g_c1, 1u);
        p = __shfl_sync(FULLMASK, p, 0);
        if (p >= 8192) break;
        const int elem = (int)p * 2 + hh;
        const float* qb = g_q + (size_t)elem * 784;
        const float* kbg = g_k + (size_t)elem * 784;

        u64 Sp[8];
#pragma unroll
        for (int e = 0; e < 8; ++e) Sp[e] = 0ull;

        int cur = 0;
        float qc = __ldg(qb + l16);
        float kc = __ldg(kbg + l16);
#pragma unroll 1
        for (int s = 0; s < 49; ++s) {
            int sn = (s < 48) ? s + 1 : 48;
            float qn = __ldg(qb + sn * 16 + l16);
            float kn = __ldg(kbg + sn * 16 + l16);

            kb[cur * 32 + lane] = kc;
            __syncwarp();
            const ulonglong2* kq = (const ulonglong2*)(kb + cur * 32 + hh * 16);
            ulonglong2 K0 = kq[0], K1 = kq[1], K2 = kq[2], K3 = kq[3];
            u64 qp = pack2(qc, qc);
            Sp[0] = ffma2(qp, K0.x, Sp[0]); Sp[1] = ffma2(qp, K0.y, Sp[1]);
            Sp[2] = ffma2(qp, K1.x, Sp[2]); Sp[3] = ffma2(qp, K1.y, Sp[3]);
            Sp[4] = ffma2(qp, K2.x, Sp[4]); Sp[5] = ffma2(qp, K2.y, Sp[5]);
            Sp[6] = ffma2(qp, K3.x, Sp[6]); Sp[7] = ffma2(qp, K3.y, Sp[7]);
            cur ^= 1;
            qc = qn; kc = kn;
        }
        {
            u64 sv = pack2(1.f / 7.f, 1.f / 7.f);
#pragma unroll
            for (int e = 0; e < 8; ++e) Sp[e] = fmul2(Sp[e], sv);
        }

        // apply S to v, softmax(16), store tok2
        float* ob = g_tok2 + (size_t)elem * 784;
        const ulonglong2* vvu = (const ulonglong2*)(g_v + (size_t)elem * 784);
        ulonglong2 U0 = __ldg(vvu + 0), U1 = __ldg(vvu + 1);
        ulonglong2 U2 = __ldg(vvu + 2), U3 = __ldg(vvu + 3);
#pragma unroll 1
        for (int s = 0; s < 49; ++s) {
            int sn = (s < 48) ? s + 1 : 48;
            ulonglong2 M0 = __ldg(vvu + sn * 4 + 0), M1 = __ldg(vvu + sn * 4 + 1);
            ulonglong2 M2 = __ldg(vvu + sn * 4 + 2), M3 = __ldg(vvu + sn * 4 + 3);

            u64 a = 0ull, b = 0ull;
            a = ffma2(Sp[0], U0.x, a); b = ffma2(Sp[1], U0.y, b);
            a = ffma2(Sp[2], U1.x, a); b = ffma2(Sp[3], U1.y, b);
            a = ffma2(Sp[4], U2.x, a); b = ffma2(Sp[5], U2.y, b);
            a = ffma2(Sp[6], U3.x, a); b = ffma2(Sp[7], U3.y, b);
            float2 f = unpack2(fadd2(a, b));
            float o = f.x + f.y;

            float m = o;
#pragma unroll
            for (int dd = 8; dd; dd >>= 1)
                m = fmaxf(m, __shfl_xor_sync(FULLMASK, m, dd, 16));
            float ex = __expf(o - m);
            float sum = ex;
#pragma unroll
            for (int dd = 8; dd; dd >>= 1)
                sum += __shfl_xor_sync(FULLMASK, sum, dd, 16);
            ob[s * 16 + l16] = __fdividef(ex, sum);
            U0 = M0; U1 = M1; U2 = M2; U3 = M3;
        }
    }
}

// ---------------------------------------------------------------------------
// qkv2: stage-2 projection only. Octet = 1 element (group-of-4 claims).
// 512 threads, 2 CTAs/SM. SMEM: 3*6272 = 18816 floats = 75264 B.
// ---------------------------------------------------------------------------
__global__ void __launch_bounds__(512, 2) qkv2(
    const float* __restrict__ WQ2,
    const float* __restrict__ WK2,
    const float* __restrict__ WV2)
{
    extern __shared__ float sm[];
    float* sW2 = sm;   // [w][s][i/4][d][4]

    const int tid = threadIdx.x;
    {
        const float* Wg[3] = {WQ2, WK2, WV2};
        for (int w = 0; w < 3; ++w) {
            const float* G = Wg[w];
            float* dst = sW2 + w * 6272;
            for (int idx = tid; idx < 6272; idx += 512) {
                int s = idx >> 7, r = idx & 127, i = r >> 3, d = r & 7;
                dst[s * 128 + (i >> 2) * 32 + d * 4 + (i & 3)] = G[(s * 8 + d) * 16 + i];
            }
        }
    }
    __syncthreads();

    const int lane = tid & 31;
    const int oct = lane >> 3;
    const int d8 = lane & 7;

    for (;;) {
        unsigned grp;
        if (lane == 0) grp = atomicAdd(&g_c2, 1u);
        grp = __shfl_sync(FULLMASK, grp, 0);
        if (grp >= 4096) break;
        const int elem = (int)grp * 4 + oct;
        const ulonglong2* pvu = (const ulonglong2*)(g_tok2 + (size_t)elem * 784);
        float* qb = g_q2 + (size_t)elem * 392;
        float* kb2 = g_k2 + (size_t)elem * 392;
        float* vb = g_v2 + (size_t)elem * 392;

#pragma unroll 2
        for (int s = 0; s < 49; ++s) {
            ulonglong2 t0 = __ldg(pvu + s * 4 + 0), t1 = __ldg(pvu + s * 4 + 1);
            ulonglong2 t2 = __ldg(pvu + s * 4 + 2), t3 = __ldg(pvu + s * 4 + 3);
            u64 P0 = t0.x, P1 = t0.y, P2 = t1.x, P3 = t1.y;
            u64 P4 = t2.x, P5 = t2.y, P6 = t3.x, P7 = t3.y;

            float q, k, v;
            PDOT(q, sW2 + s * 128 + d8 * 4, 4, 0.f);
            PDOT(k, sW2 + 6272 + s * 128 + d8 * 4, 4, 0.f);
            PDOT(v, sW2 + 12544 + s * 128 + d8 * 4, 4, 0.f);
            qb[s * 8 + d8] = q;
            kb2[s * 8 + d8] = k;
            vb[s * 8 + d8] = v;
        }
    }
}

// ---------------------------------------------------------------------------
// gram2: q2,k2 -> S(8x8) -> apply v2 -> softmax(8) -> fc1 fused -> butterfly
// -> relu -> fc2 -> out. Octet = 1 element. 1024 threads = 32 warps/SM.
// SMEM: sF1t 6272 + sF2 160 + sB1 16 + sB2 16 + kb 32*64 + hb 32*64
//     = 10560 floats = 42240 B.
// ---------------------------------------------------------------------------
__global__ void __launch_bounds__(1024, 1) gram2(
    const float* __restrict__ f1w,
    const float* __restrict__ f1b,
    const float* __restrict__ f2w,
    const float* __restrict__ f2b,
    float* __restrict__ out)
{
    extern __shared__ float sm[];
    float* sF1t = sm;           // 6272 : [d8][s][j]
    float* sF2 = sm + 6272;     // 160
    float* sB1 = sm + 6432;     // 16
    float* sB2 = sm + 6448;     // 16
    float* sKV = sm + 6464;     // 32 * 64
    float* sHB = sm + 8512;     // 32 * 64

    const int tid = threadIdx.x;
    {
        for (int idx = tid; idx < 6272; idx += 1024) {
            int d = idx / 784, r = idx - d * 784, s = r >> 4, j = r & 15;
            sF1t[(d * 49 + s) * 16 + j] = f1w[j * 392 + s * 8 + d];
        }
        for (int idx = tid; idx < 160; idx += 1024) {
            int j = idx / 10, c = idx - j * 10;
            sF2[idx] = f2w[c * 16 + j];
        }
        if (tid < 16) sB1[tid] = f1b[tid];
        if (tid < 10) sB2[tid] = f2b[tid];
    }
    __syncthreads();

    const int warpId = tid >> 5;
    const int lane = tid & 31;
    const int oct = lane >> 3;
    const int d8 = lane & 7;
    float* kb = sKV + warpId * 64;
    float* hb = sHB + warpId * 64;

    for (;;) {
        unsigned grp;
        if (lane == 0) grp = atomicAdd(&g_c3, 1u);
        grp = __shfl_sync(FULLMASK, grp, 0);
        if (grp >= 4096) break;
        const int elem = (int)grp * 4 + oct;
        const float* qb = g_q2 + (size_t)elem * 392;
        const float* kbg = g_k2 + (size_t)elem * 392;

        u64 Sp[4];
#pragma unroll
        for (int e = 0; e < 4; ++e) Sp[e] = 0ull;

        int cur = 0;
        float qc = __ldg(qb + d8);
        float kc = __ldg(kbg + d8);
#pragma unroll 1
        for (int s = 0; s < 49; ++s) {
            int sn = (s < 48) ? s + 1 : 48;
            float qn = __ldg(qb + sn * 8 + d8);
            float kn = __ldg(kbg + sn * 8 + d8);

            kb[cur * 32 + lane] = kc;
            __syncwarp();
            const ulonglong2* kq = (const ulonglong2*)(kb + cur * 32 + oct * 8);
            ulonglong2 K0 = kq[0], K1 = kq[1];
            u64 qp = pack2(qc, qc);
            Sp[0] = ffma2(qp, K0.x, Sp[0]); Sp[1] = ffma2(qp, K0.y, Sp[1]);
            Sp[2] = ffma2(qp, K1.x, Sp[2]); Sp[3] = ffma2(qp, K1.y, Sp[3]);
            cur ^= 1;
            qc = qn; kc = kn;
        }
        {
            u64 sv = pack2(1.f / 7.f, 1.f / 7.f);
#pragma unroll
            for (int e = 0; e < 4; ++e) Sp[e] = fmul2(Sp[e], sv);
        }

        // pass 2: apply S2 to v2, softmax(8), fc1 fused (packed)
        u64 Hp[8];
#pragma unroll
        for (int j = 0; j < 8; ++j) Hp[j] = 0ull;

        const ulonglong2* vvu = (const ulonglong2*)(g_v2 + (size_t)elem * 392);
        ulonglong2 U0 = __ldg(vvu + 0), U1 = __ldg(vvu + 1);
#pragma unroll 1
        for (int s = 0; s < 49; ++s) {
            int sn = (s < 48) ? s + 1 : 48;
            ulonglong2 M0 = __ldg(vvu + sn * 2 + 0), M1 = __ldg(vvu + sn * 2 + 1);

            u64 a = 0ull, b = 0ull;
            a = ffma2(Sp[0], U0.x, a); b = ffma2(Sp[1], U0.y, b);
            a = ffma2(Sp[2], U1.x, a); b = ffma2(Sp[3], U1.y, b);
            float2 f = unpack2(fadd2(a, b));
            float o = f.x + f.y;

            float m = o;
#pragma unroll
            for (int dd = 4; dd; dd >>= 1)
                m = fmaxf(m, __shfl_xor_sync(FULLMASK, m, dd, 8));
            float ex = __expf(o - m);
            float sum = ex;
#pragma unroll
            for (int dd = 4; dd; dd >>= 1)
                sum += __shfl_xor_sync(FULLMASK, sum, dd, 8);
            float tv = __fdividef(ex, sum);   // tok3[s][d8]

            const ulonglong2* wt = (const ulonglong2*)(sF1t + (d8 * 49 + s) * 16);
            ulonglong2 W0 = wt[0], W1 = wt[1], W2 = wt[2], W3 = wt[3];
            u64 tvp = pack2(tv, tv);
            Hp[0] = ffma2(tvp, W0.x, Hp[0]); Hp[1] = ffma2(tvp, W0.y, Hp[1]);
            Hp[2] = ffma2(tvp, W1.x, Hp[2]); Hp[3] = ffma2(tvp, W1.y, Hp[3]);
            Hp[4] = ffma2(tvp, W2.x, Hp[4]); Hp[5] = ffma2(tvp, W2.y, Hp[5]);
            Hp[6] = ffma2(tvp, W3.x, Hp[6]); Hp[7] = ffma2(tvp, W3.y, Hp[7]);
            U0 = M0; U1 = M1;
        }

        float h[16];
#pragma unroll
        for (int j = 0; j < 8; ++j) {
            float2 f = unpack2(Hp[j]);
            h[2 * j] = f.x; h[2 * j + 1] = f.y;
        }

        // split-butterfly reduce over the 8 octet lanes
#pragma unroll
        for (int j = 0; j < 8; ++j) {
            float sendv = (d8 & 1) ? h[j] : h[j + 8];
            float keep  = (d8 & 1) ? h[j + 8] : h[j];
            h[j] = keep + __shfl_xor_sync(FULLMASK, sendv, 1, 8);
        }
#pragma unroll
        for (int j = 0; j < 4; ++j) {
            float sendv = (d8 & 2) ? h[j] : h[j + 4];
            float keep  = (d8 & 2) ? h[j + 4] : h[j];
            h[j] = keep + __shfl_xor_sync(FULLMASK, sendv, 2, 8);
        }
#pragma unroll
        for (int j = 0; j < 2; ++j) {
            float sendv = (d8 & 4) ? h[j] : h[j + 2];
            float keep  = (d8 & 4) ? h[j + 2] : h[j];
            h[j] = keep + __shfl_xor_sync(FULLMASK, sendv, 4, 8);
        }
        int ja = 8 * (d8 & 1) + 4 * ((d8 >> 1) & 1) + 2 * ((d8 >> 2) & 1);
        __syncwarp();
        hb[oct * 16 + ja] = fmaxf(h[0] + sB1[ja], 0.f);
        hb[oct * 16 + ja + 1] = fmaxf(h[1] + sB1[ja + 1], 0.f);
        __syncwarp();

        // fc2 + softmax over 10
        const float* ho = hb + oct * 16;
        int c2 = (d8 < 2) ? (d8 + 8) : 8;
        float lg1 = sB2[d8];
        float lg2 = sB2[c2];
#pragma unroll
        for (int j = 0; j < 16; ++j) {
            float hv = ho[j];
            lg1 = fmaf(hv, sF2[j * 10 + d8], lg1);
            lg2 = fmaf(hv, sF2[j * 10 + c2], lg2);
        }
        float lg2v = (d8 < 2) ? lg2 : -1e30f;
        float m = fmaxf(lg1, lg2v);
#pragma unroll
        for (int dd = 4; dd; dd >>= 1)
            m = fmaxf(m, __shfl_xor_sync(FULLMASK, m, dd, 8));
        float e1 = __expf(lg1 - m);
        float e2 = (d8 < 2) ? __expf(lg2 - m) : 0.f;
        float sum = e1 + e2;
#pragma unroll
        for (int dd = 4; dd; dd >>= 1)
            sum += __shfl_xor_sync(FULLMASK, sum, dd, 8);
        float inv = __fdividef(1.f, sum);
        out[elem * 10 + d8] = e1 * inv;
        if (d8 < 2) out[elem * 10 + 8 + d8] = e2 * inv;
        __syncwarp();
    }
}

extern "C" void kernel_launch(void* const* d_in, const int* in_sizes, int n_in,
                              void* d_out, int out_size)
{
    (void)in_sizes; (void)n_in; (void)out_size;
    const float* x   = (const float*)d_in[0];
    const float* pe  = (const float*)d_in[1];
    const float* WQ1 = (const float*)d_in[2];
    const float* WK1 = (const float*)d_in[3];
    const float* WV1 = (const float*)d_in[4];
    const float* WQ2 = (const float*)d_in[5];
    const float* WK2 = (const float*)d_in[6];
    const float* WV2 = (const float*)d_in[7];
    const float* f1w = (const float*)d_in[8];
    const float* f1b = (const float*)d_in[9];
    const float* f2w = (const float*)d_in[10];
    const float* f2b = (const float*)d_in[11];
    float* out = (float*)d_out;

    const size_t smQ1 = (size_t)39984 * sizeof(float);  // 159936 B
    const size_t smG1 = (size_t)2048 * sizeof(float);   // 8192 B
    const size_t smQ2 = (size_t)18816 * sizeof(float);  // 75264 B
    const size_t smG2 = (size_t)10560 * sizeof(float);  // 42240 B
    cudaFuncSetAttribute(qkv1,  cudaFuncAttributeMaxDynamicSharedMemorySize, (int)smQ1);
    cudaFuncSetAttribute(gram1, cudaFuncAttributeMaxDynamicSharedMemorySize, (int)smG1);
    cudaFuncSetAttribute(qkv2,  cudaFuncAttributeMaxDynamicSharedMemorySize, (int)smQ2);
    cudaFuncSetAttribute(gram2, cudaFuncAttributeMaxDynamicSharedMemorySize, (int)smG2);

    vitP<<<(16384 * 196 + 255) / 256, 256>>>(x);
    qkv1<<<148, 640, smQ1>>>(pe, WQ1, WK1, WV1);
    gram1<<<148, 1024, smG1>>>();
    qkv2<<<296, 512, smQ2>>>(WQ2, WK2, WV2);
    gram2<<<148, 1024, smG2>>>(f1w, f1b, f2w, f2b, out);
}

// round 16
// speedup vs baseline: 1.2001x; 1.2001x over previous
#include <cuda_runtime.h>
#include <cstddef>

#define FULLMASK 0xffffffffu
typedef unsigned long long u64;

// f32x2 packed helpers (sm_103a packed fp32 pipe; 2 FMAs per instruction)
__device__ __forceinline__ u64 ffma2(u64 a, u64 b, u64 c) {
    u64 d; asm("fma.rn.f32x2 %0, %1, %2, %3;" : "=l"(d) : "l"(a), "l"(b), "l"(c)); return d;
}
__device__ __forceinline__ u64 fadd2(u64 a, u64 b) {
    u64 d; asm("add.rn.f32x2 %0, %1, %2;" : "=l"(d) : "l"(a), "l"(b)); return d;
}
__device__ __forceinline__ u64 fmul2(u64 a, u64 b) {
    u64 d; asm("mul.rn.f32x2 %0, %1, %2;" : "=l"(d) : "l"(a), "l"(b)); return d;
}
__device__ __forceinline__ u64 pack2(float lo, float hi) {
    u64 d; asm("mov.b64 %0, {%1, %2};" : "=l"(d) : "f"(lo), "f"(hi)); return d;
}
__device__ __forceinline__ float2 unpack2(u64 a) {
    float2 r; asm("mov.b64 {%0, %1}, %2;" : "=f"(r.x), "=f"(r.y) : "l"(a)); return r;
}

// Global scratch (static __device__ arrays - no allocation at runtime)
static __device__ __align__(16) float g_patch[16384 * 784];   // 51.4 MB
static __device__ __align__(16) float g_tok2[16384 * 784];    // 51.4 MB
static __device__ __align__(16) float g_v[16384 * 784];       // 51.4 MB stage1 V
static __device__ __align__(16) float g_v2[16384 * 392];      // 25.7 MB stage2 V
static __device__ unsigned g_ctrA;
static __device__ unsigned g_ctrB;

// ---------------------------------------------------------------------------
// Kernel P: grayscale + patch scatter, 4 pixels per thread + counter reset.
// ---------------------------------------------------------------------------
__global__ void vitP(const float* __restrict__ x)
{
    int t = blockIdx.x * 256 + threadIdx.x;
    if (t == 0) { g_ctrA = 0; g_ctrB = 0; }
    if (t >= 16384 * 196) return;
    int b = t / 196;
    int r = t - b * 196;          // py*7 + sx
    int py = r / 7;
    int sx = r - py * 7;
    const float4* xb = (const float4*)(x + (size_t)b * 2352);
    int off = py * 7 + sx;
    float4 c0 = __ldg(xb + off);
    float4 c1 = __ldg(xb + 196 + off);
    float4 c2 = __ldg(xb + 392 + off);
    float4 g;
    g.x = 0.299f * c0.x + 0.587f * c1.x + 0.114f * c2.x;
    g.y = 0.299f * c0.y + 0.587f * c1.y + 0.114f * c2.y;
    g.z = 0.299f * c0.z + 0.587f * c1.z + 0.114f * c2.z;
    g.w = 0.299f * c0.w + 0.587f * c1.w + 0.114f * c2.w;
    int patch = (py >> 2) * 7 + sx;
    *(float4*)(g_patch + (size_t)b * 784 + patch * 16 + (py & 3) * 4) = g;
}

// Packed 16-dot: P0..P7 (u64 pairs of the 16 inputs) against a SMEM weight
// block with quad stride QS ulonglong2's; result = scalar + bias.
#define PDOT(res, base, qs, bias) {                                          \
    const ulonglong2* _w = (const ulonglong2*)(base);                        \
    ulonglong2 _w0 = _w[0], _w1 = _w[qs], _w2 = _w[2*(qs)], _w3 = _w[3*(qs)];\
    u64 _a = 0ull, _b = 0ull;                                                \
    _a = ffma2(P0, _w0.x, _a); _b = ffma2(P1, _w0.y, _b);                    \
    _a = ffma2(P2, _w1.x, _a); _b = ffma2(P3, _w1.y, _b);                    \
    _a = ffma2(P4, _w2.x, _a); _b = ffma2(P5, _w2.y, _b);                    \
    _a = ffma2(P6, _w3.x, _a); _b = ffma2(P7, _w3.y, _b);                    \
    float2 _f = unpack2(fadd2(_a, _b));                                      \
    res = _f.x + _f.y + (bias); }

// ---------------------------------------------------------------------------
// Kernel A (stage 1): single-pass QKV (packed f32x2 math) -> gram S (k via
// SMEM broadcast) -> v to g_v. Pass 2: v back (prefetched), apply S,
// softmax(16) -> tok2. Warp = 2 half-warps = 2 elements. 640 threads.
// SMEM: 3*12544 + 3*784 + 20*64 = 41264 floats = 165056 B.
// ---------------------------------------------------------------------------
__global__ void __launch_bounds__(640, 1) vitA(
    const float* __restrict__ pe,
    const float* __restrict__ WQ1,
    const float* __restrict__ WK1,
    const float* __restrict__ WV1)
{
    extern __shared__ float sm[];
    float* sW = sm;          // 3 * 12544, layout [w][s][i/4][o][4]
    float* sB = sm + 37632;  // 3 * 784
    float* sKV = sm + 39984; // 20 warps * 64

    const int tid = threadIdx.x;
    {
        const float* Wg[3] = {WQ1, WK1, WV1};
        for (int w = 0; w < 3; ++w) {
            const float* G = Wg[w];
            float* dst = sW + w * 12544;
            for (int idx = tid; idx < 12544; idx += 640) {
                int s = idx >> 8, r = idx & 255, i = r >> 4, o = r & 15;
                dst[s * 256 + (i >> 2) * 64 + o * 4 + (i & 3)] = G[(s * 16 + o) * 32 + i];
            }
            float* db = sB + w * 784;
            for (int idx = tid; idx < 784; idx += 640) {
                int s = idx >> 4, o = idx & 15;
                const float* gw = G + (s * 16 + o) * 32 + 16;
                const float* pp = pe + s * 16;
                float acc = 0.f;
#pragma unroll
                for (int j = 0; j < 16; ++j) acc = fmaf(pp[j], gw[j], acc);
                db[idx] = acc;
            }
        }
    }
    __syncthreads();

    const int warpId = tid >> 5;
    const int lane = tid & 31;
    const int hh = lane >> 4;
    const int l16 = lane & 15;
    float* kb = sKV + warpId * 64;   // [buf 0/1][lane]

    for (;;) {
        unsigned p;
        if (lane == 0) p = atomicAdd(&g_ctrA, 1u);
        p = __shfl_sync(FULLMASK, p, 0);
        if (p >= 8192) break;
        const int elem = (int)p * 2 + hh;
        const float* pb = g_patch + (size_t)elem * 784;
        float* vb = g_v + (size_t)elem * 784;
        const ulonglong2* pvu = (const ulonglong2*)pb;

        u64 Sp[8];
#pragma unroll
        for (int e = 0; e < 8; ++e) Sp[e] = 0ull;

        int cur = 0;
        ulonglong2 t0 = __ldg(pvu + 0), t1 = __ldg(pvu + 1);
        ulonglong2 t2 = __ldg(pvu + 2), t3 = __ldg(pvu + 3);
        u64 P0 = t0.x, P1 = t0.y, P2 = t1.x, P3 = t1.y;
        u64 P4 = t2.x, P5 = t2.y, P6 = t3.x, P7 = t3.y;

        // ---- pass 1: q,k,v per s; gram S; store v ----
#pragma unroll 1
        for (int s = 0; s < 49; ++s) {
            int sn = (s < 48) ? s + 1 : 48;
            ulonglong2 n0 = __ldg(pvu + sn * 4 + 0), n1 = __ldg(pvu + sn * 4 + 1);
            ulonglong2 n2 = __ldg(pvu + sn * 4 + 2), n3 = __ldg(pvu + sn * 4 + 3);

            float q, k, v;
            PDOT(q, sW + s * 256 + l16 * 4, 8, sB[s * 16 + l16]);
            PDOT(k, sW + 12544 + s * 256 + l16 * 4, 8, sB[784 + s * 16 + l16]);
            PDOT(v, sW + 25088 + s * 256 + l16 * 4, 8, sB[1568 + s * 16 + l16]);
            vb[s * 16 + l16] = v;

            kb[cur * 32 + lane] = k;
            __syncwarp();
            const ulonglong2* kq = (const ulonglong2*)(kb + cur * 32 + hh * 16);
            ulonglong2 K0 = kq[0], K1 = kq[1], K2 = kq[2], K3 = kq[3];
            u64 qp = pack2(q, q);
            Sp[0] = ffma2(qp, K0.x, Sp[0]); Sp[1] = ffma2(qp, K0.y, Sp[1]);
            Sp[2] = ffma2(qp, K1.x, Sp[2]); Sp[3] = ffma2(qp, K1.y, Sp[3]);
            Sp[4] = ffma2(qp, K2.x, Sp[4]); Sp[5] = ffma2(qp, K2.y, Sp[5]);
            Sp[6] = ffma2(qp, K3.x, Sp[6]); Sp[7] = ffma2(qp, K3.y, Sp[7]);
            cur ^= 1;
            P0 = n0.x; P1 = n0.y; P2 = n1.x; P3 = n1.y;
            P4 = n2.x; P5 = n2.y; P6 = n3.x; P7 = n3.y;
        }
        {
            u64 sv = pack2(1.f / 7.f, 1.f / 7.f);
#pragma unroll
            for (int e = 0; e < 8; ++e) Sp[e] = fmul2(Sp[e], sv);
        }

        __syncwarp();  // v stores visible to all lanes of the warp

        // ---- pass 2: read v, apply S, softmax(16) -> tok2 ----
        float* ob = g_tok2 + (size_t)elem * 784;
        const ulonglong2* vvu = (const ulonglong2*)vb;
        ulonglong2 U0 = vvu[0], U1 = vvu[1], U2 = vvu[2], U3 = vvu[3];
#pragma unroll 1
        for (int s = 0; s < 49; ++s) {
            int sn = (s < 48) ? s + 1 : 48;
            ulonglong2 M0 = vvu[sn * 4 + 0], M1 = vvu[sn * 4 + 1];
            ulonglong2 M2 = vvu[sn * 4 + 2], M3 = vvu[sn * 4 + 3];

            u64 a = 0ull, b = 0ull;
            a = ffma2(Sp[0], U0.x, a); b = ffma2(Sp[1], U0.y, b);
            a = ffma2(Sp[2], U1.x, a); b = ffma2(Sp[3], U1.y, b);
            a = ffma2(Sp[4], U2.x, a); b = ffma2(Sp[5], U2.y, b);
            a = ffma2(Sp[6], U3.x, a); b = ffma2(Sp[7], U3.y, b);
            float2 f = unpack2(fadd2(a, b));
            float o = f.x + f.y;

            float m = o;
#pragma unroll
            for (int dd = 8; dd; dd >>= 1)
                m = fmaxf(m, __shfl_xor_sync(FULLMASK, m, dd, 16));
            float ex = __expf(o - m);
            float sum = ex;
#pragma unroll
            for (int dd = 8; dd; dd >>= 1)
                sum += __shfl_xor_sync(FULLMASK, sum, dd, 16);
            ob[s * 16 + l16] = __fdividef(ex, sum);
            U0 = M0; U1 = M1; U2 = M2; U3 = M3;
        }
    }
}

// ---------------------------------------------------------------------------
// Kernel B: tok2 -> QKV2 (packed) -> attn(8) -> softmax -> fc1 fused (packed)
// -> octet butterfly -> relu -> fc2 -> out. Warp = 4 octets = 4 elements.
// 512 threads, 2 CTAs/SM (32 warps/SM), grid 296.
// SMEM: 18816 + 6272 + 160 + 32 + 16*64 + 16*64 = 27328 fl = 109312 B (< 113.6 KB).
// ---------------------------------------------------------------------------
__global__ void __launch_bounds__(512, 2) vitB(
    const float* __restrict__ WQ2,
    const float* __restrict__ WK2,
    const float* __restrict__ WV2,
    const float* __restrict__ f1w,
    const float* __restrict__ f1b,
    const float* __restrict__ f2w,
    const float* __restrict__ f2b,
    float* __restrict__ out)
{
    extern __shared__ float sm[];
    float* sW2 = sm;            // 3 * 6272, [w][s][i/4][d][4]
    float* sF1t = sm + 18816;   // 6272 : [d8][s][j]
    float* sF2 = sm + 25088;    // 160
    float* sB1 = sm + 25248;    // 16
    float* sB2 = sm + 25264;    // 16
    float* sKV = sm + 25280;    // 16 * 64
    float* sHB = sm + 26304;    // 16 * 64

    const int tid = threadIdx.x;
    {
        const float* Wg[3] = {WQ2, WK2, WV2};
        for (int w = 0; w < 3; ++w) {
            const float* G = Wg[w];
            float* dst = sW2 + w * 6272;
            for (int idx = tid; idx < 6272; idx += 512) {
                int s = idx >> 7, r = idx & 127, i = r >> 3, d = r & 7;
                dst[s * 128 + (i >> 2) * 32 + d * 4 + (i & 3)] = G[(s * 8 + d) * 16 + i];
            }
        }
        for (int idx = tid; idx < 6272; idx += 512) {
            int d = idx / 784, r = idx - d * 784, s = r >> 4, j = r & 15;
            sF1t[(d * 49 + s) * 16 + j] = f1w[j * 392 + s * 8 + d];
        }
        for (int idx = tid; idx < 160; idx += 512) {
            int j = idx / 10, c = idx - j * 10;
            sF2[idx] = f2w[c * 16 + j];
        }
        if (tid < 16) sB1[tid] = f1b[tid];
        if (tid < 10) sB2[tid] = f2b[tid];
    }
    __syncthreads();

    const int warpId = tid >> 5;
    const int lane = tid & 31;
    const int oct = lane >> 3;   // element within group
    const int d8 = lane & 7;     // output dim
    float* kb = sKV + warpId * 64;
    float* hb = sHB + warpId * 64;

    for (;;) {
        unsigned grp;
        if (lane == 0) grp = atomicAdd(&g_ctrB, 1u);
        grp = __shfl_sync(FULLMASK, grp, 0);
        if (grp >= 4096) break;
        const int elem = (int)grp * 4 + oct;
        const float* tb = g_tok2 + (size_t)elem * 784;
        float* vb = g_v2 + (size_t)elem * 392;
        const ulonglong2* pvu = (const ulonglong2*)tb;

        u64 Sp[4];
#pragma unroll
        for (int e = 0; e < 4; ++e) Sp[e] = 0ull;

        int cur = 0;
        ulonglong2 t0 = __ldg(pvu + 0), t1 = __ldg(pvu + 1);
        ulonglong2 t2 = __ldg(pvu + 2), t3 = __ldg(pvu + 3);
        u64 P0 = t0.x, P1 = t0.y, P2 = t1.x, P3 = t1.y;
        u64 P4 = t2.x, P5 = t2.y, P6 = t3.x, P7 = t3.y;

        // ---- pass 1: q2,k2,v2 per s; gram; store v2 ----
#pragma unroll 1
        for (int s = 0; s < 49; ++s) {
            int sn = (s < 48) ? s + 1 : 48;
            ulonglong2 n0 = __ldg(pvu + sn * 4 + 0), n1 = __ldg(pvu + sn * 4 + 1);
            ulonglong2 n2 = __ldg(pvu + sn * 4 + 2), n3 = __ldg(pvu + sn * 4 + 3);

            float q, k, v;
            PDOT(q, sW2 + s * 128 + d8 * 4, 4, 0.f);
            PDOT(k, sW2 + 6272 + s * 128 + d8 * 4, 4, 0.f);
            PDOT(v, sW2 + 12544 + s * 128 + d8 * 4, 4, 0.f);
            vb[s * 8 + d8] = v;

            kb[cur * 32 + lane] = k;
            __syncwarp();
            const ulonglong2* kq = (const ulonglong2*)(kb + cur * 32 + oct * 8);
            ulonglong2 K0 = kq[0], K1 = kq[1];
            u64 qp = pack2(q, q);
            Sp[0] = ffma2(qp, K0.x, Sp[0]); Sp[1] = ffma2(qp, K0.y, Sp[1]);
            Sp[2] = ffma2(qp, K1.x, Sp[2]); Sp[3] = ffma2(qp, K1.y, Sp[3]);
            cur ^= 1;
            P0 = n0.x; P1 = n0.y; P2 = n1.x; P3 = n1.y;
            P4 = n2.x; P5 = n2.y; P6 = n3.x; P7 = n3.y;
        }
        {
            u64 sv = pack2(1.f / 7.f, 1.f / 7.f);
#pragma unroll
            for (int e = 0; e < 4; ++e) Sp[e] = fmul2(Sp[e], sv);
        }

        __syncwarp();  // v2 stores visible warp-wide

        // ---- pass 2: read v2, apply S2, softmax(8), fc1 fused (packed) ----
        u64 Hp[8];
#pragma unroll
        for (int j = 0; j < 8; ++j) Hp[j] = 0ull;

        const ulonglong2* vvu = (const ulonglong2*)vb;
        ulonglong2 U0 = vvu[0], U1 = vvu[1];
#pragma unroll 1
        for (int s = 0; s < 49; ++s) {
            int sn = (s < 48) ? s + 1 : 48;
            ulonglong2 M0 = vvu[sn * 2 + 0], M1 = vvu[sn * 2 + 1];

            u64 a = 0ull, b = 0ull;
            a = ffma2(Sp[0], U0.x, a); b = ffma2(Sp[1], U0.y, b);
            a = ffma2(Sp[2], U1.x, a); b = ffma2(Sp[3], U1.y, b);
            float2 f = unpack2(fadd2(a, b));
            float o = f.x + f.y;

            float m = o;
#pragma unroll
            for (int dd = 4; dd; dd >>= 1)
                m = fmaxf(m, __shfl_xor_sync(FULLMASK, m, dd, 8));
            float ex = __expf(o - m);
            float sum = ex;
#pragma unroll
            for (int dd = 4; dd; dd >>= 1)
                sum += __shfl_xor_sync(FULLMASK, sum, dd, 8);
            float tv = __fdividef(ex, sum);   // tok3[s][d8]

            const ulonglong2* wt = (const ulonglong2*)(sF1t + (d8 * 49 + s) * 16);
            ulonglong2 W0 = wt[0], W1 = wt[1];
            u64 tvp = pack2(tv, tv);
            Hp[0] = ffma2(tvp, W0.x, Hp[0]); Hp[1] = ffma2(tvp, W0.y, Hp[1]);
            Hp[2] = ffma2(tvp, W1.x, Hp[2]); Hp[3] = ffma2(tvp, W1.y, Hp[3]);
            const ulonglong2* wt2 = wt + 2;
            ulonglong2 W2 = wt2[0], W3 = wt2[1];
            Hp[4] = ffma2(tvp, W2.x, Hp[4]); Hp[5] = ffma2(tvp, W2.y, Hp[5]);
            Hp[6] = ffma2(tvp, W3.x, Hp[6]); Hp[7] = ffma2(tvp, W3.y, Hp[7]);
            U0 = M0; U1 = M1;
        }

        float h[16];
#pragma unroll
        for (int j = 0; j < 8; ++j) {
            float2 f = unpack2(Hp[j]);
            h[2 * j] = f.x; h[2 * j + 1] = f.y;
        }

        // split-butterfly reduce over the 8 octet lanes: 14 shfl total
#pragma unroll
        for (int j = 0; j < 8; ++j) {
            float sendv = (d8 & 1) ? h[j] : h[j + 8];
            float keep  = (d8 & 1) ? h[j + 8] : h[j];
            h[j] = keep + __shfl_xor_sync(FULLMASK, sendv, 1, 8);
        }
#pragma unroll
        for (int j = 0; j < 4; ++j) {
            float sendv = (d8 & 2) ? h[j] : h[j + 4];
            float keep  = (d8 & 2) ? h[j + 4] : h[j];
            h[j] = keep + __shfl_xor_sync(FULLMASK, sendv, 2, 8);
        }
#pragma unroll
        for (int j = 0; j < 2; ++j) {
            float sendv = (d8 & 4) ? h[j] : h[j + 2];
            float keep  = (d8 & 4) ? h[j + 2] : h[j];
            h[j] = keep + __shfl_xor_sync(FULLMASK, sendv, 4, 8);
        }
        int ja = 8 * (d8 & 1) + 4 * ((d8 >> 1) & 1) + 2 * ((d8 >> 2) & 1);
        __syncwarp();
        hb[oct * 16 + ja] = fmaxf(h[0] + sB1[ja], 0.f);
        hb[oct * 16 + ja + 1] = fmaxf(h[1] + sB1[ja + 1], 0.f);
        __syncwarp();

        // ---- fc2 + softmax over 10 (octet-local) ----
        const float* ho = hb + oct * 16;
        int c2 = (d8 < 2) ? (d8 + 8) : 8;
        float lg1 = sB2[d8];
        float lg2 = sB2[c2];
#pragma unroll
        for (int j = 0; j < 16; ++j) {
            float hv = ho[j];
            lg1 = fmaf(hv, sF2[j * 10 + d8], lg1);
            lg2 = fmaf(hv, sF2[j * 10 + c2], lg2);
        }
        float lg2v = (d8 < 2) ? lg2 : -1e30f;
        float m = fmaxf(lg1, lg2v);
#pragma unroll
        for (int dd = 4; dd; dd >>= 1)
            m = fmaxf(m, __shfl_xor_sync(FULLMASK, m, dd, 8));
        float e1 = __expf(lg1 - m);
        float e2 = (d8 < 2) ? __expf(lg2 - m) : 0.f;
        float sum = e1 + e2;
#pragma unroll
        for (int dd = 4; dd; dd >>= 1)
            sum += __shfl_xor_sync(FULLMASK, sum, dd, 8);
        float inv = __fdividef(1.f, sum);
        out[elem * 10 + d8] = e1 * inv;
        if (d8 < 2) out[elem * 10 + 8 + d8] = e2 * inv;
        __syncwarp();  // protect hb before next iteration
    }
}

extern "C" void kernel_launch(void* const* d_in, const int* in_sizes, int n_in,
                              void* d_out, int out_size)
{
    (void)in_sizes; (void)n_in; (void)out_size;
    const float* x   = (const float*)d_in[0];
    const float* pe  = (const float*)d_in[1];
    const float* WQ1 = (const float*)d_in[2];
    const float* WK1 = (const float*)d_in[3];
    const float* WV1 = (const float*)d_in[4];
    const float* WQ2 = (const float*)d_in[5];
    const float* WK2 = (const float*)d_in[6];
    const float* WV2 = (const float*)d_in[7];
    const float* f1w = (const float*)d_in[8];
    const float* f1b = (const float*)d_in[9];
    const float* f2w = (const float*)d_in[10];
    const float* f2b = (const float*)d_in[11];
    float* out = (float*)d_out;

    const size_t smA = (size_t)41264 * sizeof(float);  // 165056 B
    const size_t smB = (size_t)27328 * sizeof(float);  // 109312 B
    cudaFuncSetAttribute(vitA, cudaFuncAttributeMaxDynamicSharedMemorySize, (int)smA);
    cudaFuncSetAttribute(vitB, cudaFuncAttributeMaxDynamicSharedMemorySize, (int)smB);

    vitP<<<(16384 * 196 + 255) / 256, 256>>>(x);
    vitA<<<148, 640, smA>>>(pe, WQ1, WK1, WV1);
    vitB<<<296, 512, smB>>>(WQ2, WK2, WV2, f1w, f1b, f2w, f2b, out);
}